// round 13
// baseline (speedup 1.0000x reference)
#include <cuda_runtime.h>
#include <cuda_fp16.h>
#include <cstdint>
#include <math.h>

// ---------------- scratch ----------------
__device__ float g_x [4194304];
__device__ float g_h [4194304];   // ln out: half
__device__ float g_q [4194304];   // half codes
__device__ float g_k [4194304];
__device__ float g_v [4194304];
__device__ float g_o [4194304];   // half attn out
__device__ float g_vt[4194304];   // half v^T codes
__device__ float g_gg[16777216];  // half GEGLU out
__device__ float g_w [27262976];  // half weights (reinterpret)
__device__ float g_cs[163840];    // half ctx

// ---------------- helpers ----------------
static __device__ __forceinline__ uint32_t smem_u32(const void* p) {
    uint32_t a;
    asm("{ .reg .u64 t; cvta.to.shared.u64 t, %1; cvt.u32.u64 %0, t; }" : "=r"(a) : "l"(p));
    return a;
}
#define MMAH(d, a, b) \
    asm volatile("mma.sync.aligned.m16n8k16.row.col.f32.f16.f16.f32 " \
        "{%0,%1,%2,%3},{%4,%5,%6,%7},{%8,%9},{%0,%1,%2,%3};" \
        : "+f"((d)[0]), "+f"((d)[1]), "+f"((d)[2]), "+f"((d)[3]) \
        : "r"((a)[0]), "r"((a)[1]), "r"((a)[2]), "r"((a)[3]), "r"((b)[0]), "r"((b)[1]))
#define LDSM4(r0, r1, r2, r3, addr) \
    asm volatile("ldmatrix.sync.aligned.m8n8.x4.shared.b16 {%0,%1,%2,%3}, [%4];" \
        : "=r"(r0), "=r"(r1), "=r"(r2), "=r"(r3) : "r"(addr))
#define CPA(dst, src, sz) \
    asm volatile("cp.async.cg.shared.global [%0], [%1], 16, %2;" :: "r"(dst), "l"(src), "r"(sz))
static __device__ __forceinline__ uint32_t packh2(float a, float b) {
    __half2 h = __floats2half2_rn(a, b);
    return *reinterpret_cast<uint32_t*>(&h);
}
static __device__ __forceinline__ float gelu(float g) {
    return 0.5f * g * (1.f + erff(g * 0.70710678118654752440f));
}

// ================= fused attention (two-pass, max-free softmax) =================
__global__ void __launch_bounds__(256)
fattn(const __half* __restrict__ q, const __half* __restrict__ k,
      const __half* __restrict__ vt, __half* __restrict__ o,
      int Tq, int Tk, int Tkpad,
      const float* __restrict__ dqp, const float* __restrict__ dkp,
      const float* __restrict__ dwp, const float* __restrict__ dvp)
{
    constexpr int QS = 128 * 72, KS = 128 * 72, VS = 64 * 136;
    extern __shared__ __half sh[];
    const uint32_t smb = smem_u32(sh);
    const uint32_t kb_ = smb + QS * 2, vb_ = smb + (QS + 2 * KS) * 2;

    const int tid = threadIdx.x, wid = tid >> 5, lane = tid & 31;
    const int grp = lane >> 2, tg = lane & 3;
    const int lm = lane & 7, lmat = lane >> 3;
    const int bh = blockIdx.z, b = bh >> 4, h = bh & 15;
    const int m0 = blockIdx.x * 128;
    const int nkt = (Tk + 127) >> 7;

    const float alpha = 0.125f * __ldg(dqp) * __ldg(dkp);
    const float dw = __ldg(dwp);
    const float beta = dw * __ldg(dvp);

    const uint32_t qOff = ((uint32_t)((wid * 16 + (lmat & 1) * 8 + lm) * 72 + ((lmat >> 1) << 3))) * 2;
    uint32_t kOff[8], vOff[4];
#pragma unroll
    for (int p = 0; p < 8; ++p)
        kOff[p] = ((uint32_t)((p * 16 + (lmat >> 1) * 8 + lm) * 72 + ((lmat & 1) << 3))) * 2;
#pragma unroll
    for (int p = 0; p < 4; ++p)
        vOff[p] = ((uint32_t)((p * 16 + (lmat >> 1) * 8 + lm) * 136 + ((lmat & 1) << 3))) * 2;

    {
        const __half* qb = q + ((long long)b * Tq + m0) * 1024 + h * 64;
#pragma unroll
        for (int i = 0; i < 4; ++i) {
            const int idx = tid + (i << 8);
            const int r = idx >> 3, c = idx & 7;
            CPA(smb + (uint32_t)(r * 72 + (c << 3)) * 2, qb + (long long)r * 1024 + (c << 3), 16);
        }
    }

    auto loadK = [&](int t, int st) {
        const __half* kbase = k + ((long long)b * Tk) * 1024 + h * 64;
#pragma unroll
        for (int i = 0; i < 4; ++i) {
            const int idx = tid + (i << 8);
            const int r = idx >> 3, c = idx & 7;
            const int key = t * 128 + r;
            const int ok = key < Tk;
            const __half* s = ok ? (kbase + (long long)key * 1024 + (c << 3)) : kbase;
            CPA(kb_ + (uint32_t)(st * KS + r * 72 + (c << 3)) * 2, s, ok ? 16 : 0);
        }
    };
    auto loadV = [&](int t, int st) {
        const __half* vbase = vt + ((long long)bh * 64) * Tkpad;
#pragma unroll
        for (int i = 0; i < 4; ++i) {
            const int idx = tid + (i << 8);
            const int r = idx >> 4, c = idx & 15;
            const int key = t * 128 + (c << 3);
            const int ok = (key + 8) <= Tkpad;
            const __half* s = ok ? (vbase + (long long)r * Tkpad + key) : vbase;
            CPA(vb_ + (uint32_t)(st * VS + r * 136 + (c << 3)) * 2, s, ok ? 16 : 0);
        }
    };

    float sacc[16][4];
    auto computeS = [&](int st) {
#pragma unroll
        for (int nf = 0; nf < 16; ++nf)
#pragma unroll
            for (int e = 0; e < 4; ++e) sacc[nf][e] = 0.f;
        const uint32_t kB = kb_ + (uint32_t)st * KS * 2;
#pragma unroll
        for (int kc = 0; kc < 4; ++kc) {
            const uint32_t kb2 = (uint32_t)(kc << 5);
            uint32_t ah[4];
            LDSM4(ah[0], ah[1], ah[2], ah[3], smb + qOff + kb2);
            uint32_t bf[16][2];
#pragma unroll
            for (int p = 0; p < 8; ++p)
                LDSM4(bf[2*p][0], bf[2*p][1], bf[2*p+1][0], bf[2*p+1][1], kB + kOff[p] + kb2);
#pragma unroll
            for (int nf = 0; nf < 16; ++nf) MMAH(sacc[nf], ah, bf[nf]);
        }
    };

    // ---- pass 1 ----
    float psum0 = 0.f, psum1 = 0.f;
    loadK(0, 0);
    asm volatile("cp.async.commit_group;");
    for (int t = 0; t < nkt; ++t) {
        if (t + 1 < nkt) loadK(t + 1, (t + 1) & 1);
        asm volatile("cp.async.commit_group;");
        if (t + 1 < nkt) asm volatile("cp.async.wait_group 1;");
        else             asm volatile("cp.async.wait_group 0;");
        __syncthreads();
        computeS(t & 1);
        __syncthreads();
        const int cb = t * 128;
#pragma unroll
        for (int nf = 0; nf < 16; ++nf) {
            const int c0 = cb + nf * 8 + (tg << 1);
            if (c0 < Tk)     { psum0 += expf(sacc[nf][0] * alpha); psum1 += expf(sacc[nf][2] * alpha); }
            if (c0 + 1 < Tk) { psum0 += expf(sacc[nf][1] * alpha); psum1 += expf(sacc[nf][3] * alpha); }
        }
    }
    psum0 += __shfl_xor_sync(0xffffffffu, psum0, 1);
    psum0 += __shfl_xor_sync(0xffffffffu, psum0, 2);
    psum1 += __shfl_xor_sync(0xffffffffu, psum1, 1);
    psum1 += __shfl_xor_sync(0xffffffffu, psum1, 2);

    // ---- pass 2 ----
    float oacc[8][4];
#pragma unroll
    for (int i = 0; i < 8; ++i)
#pragma unroll
        for (int e = 0; e < 4; ++e) oacc[i][e] = 0.f;

    loadK(0, 0); loadV(0, 0);
    asm volatile("cp.async.commit_group;");
    for (int t = 0; t < nkt; ++t) {
        if (t + 1 < nkt) { loadK(t + 1, (t + 1) & 1); loadV(t + 1, (t + 1) & 1); }
        asm volatile("cp.async.commit_group;");
        if (t + 1 < nkt) asm volatile("cp.async.wait_group 1;");
        else             asm volatile("cp.async.wait_group 0;");
        __syncthreads();
        computeS(t & 1);
        const uint32_t vB = vb_ + (uint32_t)(t & 1) * VS * 2;
        const int cb = t * 128;
#pragma unroll
        for (int kb = 0; kb < 8; ++kb) {
            uint32_t ah[4];
#pragma unroll
            for (int hf = 0; hf < 2; ++hf) {
                const int nf = 2 * kb + hf;
                const int c0 = cb + nf * 8 + (tg << 1);
                const int ok0 = c0 < Tk, ok1 = (c0 + 1) < Tk;
                float p0 = ok0 ? expf(sacc[nf][0] * alpha) / psum0 : 0.f;
                float p1 = ok1 ? expf(sacc[nf][1] * alpha) / psum0 : 0.f;
                float p2 = ok0 ? expf(sacc[nf][2] * alpha) / psum1 : 0.f;
                float p3 = ok1 ? expf(sacc[nf][3] * alpha) / psum1 : 0.f;
                const float q0 = fminf(fmaxf(rintf(p0 / dw), 0.f), 255.f);
                const float q1 = fminf(fmaxf(rintf(p1 / dw), 0.f), 255.f);
                const float q2 = fminf(fmaxf(rintf(p2 / dw), 0.f), 255.f);
                const float q3 = fminf(fmaxf(rintf(p3 / dw), 0.f), 255.f);
                ah[hf * 2]     = packh2(q0, q1);
                ah[hf * 2 + 1] = packh2(q2, q3);
            }
            const uint32_t kb2 = (uint32_t)(kb << 5);
            uint32_t bf[8][2];
#pragma unroll
            for (int p = 0; p < 4; ++p)
                LDSM4(bf[2*p][0], bf[2*p][1], bf[2*p+1][0], bf[2*p+1][1], vB + vOff[p] + kb2);
#pragma unroll
            for (int nfo = 0; nfo < 8; ++nfo) MMAH(oacc[nfo], ah, bf[nfo]);
        }
        __syncthreads();
    }

    const int row0 = m0 + wid * 16 + grp;
    __half* ob = o + ((long long)b * Tq) * 1024 + h * 64;
#pragma unroll
    for (int nfo = 0; nfo < 8; ++nfo) {
        const int c = nfo * 8 + (tg << 1);
        *reinterpret_cast<__half2*>(ob + (long long)row0 * 1024 + c) =
            __floats2half2_rn(oacc[nfo][0] * beta, oacc[nfo][1] * beta);
        *reinterpret_cast<__half2*>(ob + (long long)(row0 + 8) * 1024 + c) =
            __floats2half2_rn(oacc[nfo][2] * beta, oacc[nfo][3] * beta);
    }
}

// ================= fp16 mma GEMM (3-stage cp.async pipeline) =================
struct HArgs {
    const __half *A, *B; void *C, *C2, *C3;
    int M, N, Nstore, K, lda, ldb, ldc, ldr;
    const float *bias, *res, *s1, *s2, *qd, *qd2, *qd3;
    float s0;
};

static __device__ __forceinline__ int geglu_src(int n) {
    const int gp = n >> 4, r = n & 15;
    return (r < 8) ? (gp * 8 + r) : (4096 + gp * 8 + (r - 8));
}

template<int BN, int WM, int BK, bool CHALF, bool GEGLU, bool QKV>
__global__ void __launch_bounds__(256)
hgemm(const __grid_constant__ HArgs g)
{
    constexpr int WN = 8 / WM, WTM = 128 / WM, WTN = BN / WN;
    constexpr int MF = WTM / 16, NF = WTN / 8;
    constexpr int SB = BK + 8;
    constexpr int AS = 128 * SB, BS = BN * SB;
    constexpr int STG = AS + BS;
    constexpr int KPC = BK / 8;
    constexpr int KK  = BK / 16;

    extern __shared__ __half smh[];
    const uint32_t smb = smem_u32(smh);
    const int tid = threadIdx.x, wid = tid >> 5, lane = tid & 31;
    const int grp = lane >> 2, tg = lane & 3;
    const int lm = lane & 7, lmat = lane >> 3;
    const int wm = wid / WN, wn = wid % WN;

    const int bm = blockIdx.y * 128, bn = blockIdx.x * BN;
    const int nch = g.K / BK;

    uint32_t aOff[MF], bOff[NF / 2];
#pragma unroll
    for (int mf = 0; mf < MF; ++mf)
        aOff[mf] = ((uint32_t)((wm * WTM + mf * 16 + (lmat & 1) * 8 + lm) * SB + ((lmat >> 1) << 3))) * 2;
#pragma unroll
    for (int p = 0; p < NF / 2; ++p)
        bOff[p] = ((uint32_t)((wn * WTN + p * 16 + (lmat >> 1) * 8 + lm) * SB + ((lmat & 1) << 3))) * 2;

    float acc[MF][NF][4];
#pragma unroll
    for (int i = 0; i < MF; ++i)
#pragma unroll
        for (int j = 0; j < NF; ++j)
#pragma unroll
            for (int c = 0; c < 4; ++c) acc[i][j][c] = 0.f;

    auto issue = [&](int ch, int st) {
        const int k0 = ch * BK;
        const uint32_t sa = smb + (uint32_t)st * STG * 2;
#pragma unroll
        for (int i = 0; i < 128 * KPC / 256; ++i) {
            const int idx = tid + (i << 8);
            const int r = idx / KPC, c = idx % KPC;
            const int gr = bm + r, ok = (gr < g.M);
            const __half* s = ok ? (g.A + (long long)gr * g.lda + k0 + (c << 3)) : g.A;
            CPA(sa + (uint32_t)(r * SB + (c << 3)) * 2, s, ok ? 16 : 0);
        }
#pragma unroll
        for (int i = 0; i < BN * KPC / 256; ++i) {
            const int idx = tid + (i << 8);
            const int r = idx / KPC, c = idx % KPC;
            const int gn = bn + r, ok = (gn < g.N);
            const int srow = GEGLU ? geglu_src(gn) : gn;
            const __half* s = ok ? (g.B + (long long)srow * g.ldb + k0 + (c << 3)) : g.B;
            CPA(sa + (uint32_t)(AS + r * SB + (c << 3)) * 2, s, ok ? 16 : 0);
        }
    };

    auto compute = [&](int st) {
        const uint32_t aB = smb + (uint32_t)st * STG * 2;
        const uint32_t bB = aB + (uint32_t)AS * 2;
#pragma unroll
        for (int kk = 0; kk < KK; ++kk) {
            const uint32_t kb2 = (uint32_t)(kk << 5);
            uint32_t bh[NF][2];
#pragma unroll
            for (int p = 0; p < NF / 2; ++p)
                LDSM4(bh[2*p][0], bh[2*p][1], bh[2*p+1][0], bh[2*p+1][1], bB + bOff[p] + kb2);
#pragma unroll
            for (int mf = 0; mf < MF; ++mf) {
                uint32_t ah[4];
                LDSM4(ah[0], ah[1], ah[2], ah[3], aB + aOff[mf] + kb2);
#pragma unroll
                for (int nf = 0; nf < NF; ++nf) MMAH(acc[mf][nf], ah, bh[nf]);
            }
        }
    };

    // 3-stage pipeline: one __syncthreads per chunk.
    // group i <-> chunk i (commit only when issuing).
    issue(0, 0);
    asm volatile("cp.async.commit_group;");
    if (nch > 1) {
        issue(1, 1);
        asm volatile("cp.async.commit_group;");
    }
    for (int ch = 0; ch < nch; ++ch) {
        if (ch + 1 < nch) asm volatile("cp.async.wait_group 1;");
        else              asm volatile("cp.async.wait_group 0;");
        __syncthreads();              // chunk ch visible to all; all warps done with buf (ch+2)%3
        if (ch + 2 < nch) {
            issue(ch + 2, (ch + 2) % 3);
            asm volatile("cp.async.commit_group;");
        }
        compute(ch % 3);
    }

    if (GEGLU) {
#pragma unroll
        for (int mf = 0; mf < MF; ++mf) {
            const int r0 = bm + wm * WTM + (mf << 4) + grp;
#pragma unroll
            for (int p = 0; p < NF / 2; ++p) {
                const int va = bn + wn * WTN + (p << 4) + (tg << 1);
                const int oc = ((va >> 4) << 3) + (va & 7);
                const float ba0 = __ldg(g.bias + oc),        ba1 = __ldg(g.bias + oc + 1);
                const float bg0 = __ldg(g.bias + 4096 + oc), bg1 = __ldg(g.bias + 4096 + oc + 1);
                float* A2 = acc[mf][2 * p];
                float* G2 = acc[mf][2 * p + 1];
#pragma unroll
                for (int hrow = 0; hrow < 2; ++hrow) {
                    const int r = r0 + hrow * 8;
                    const float a0 = A2[hrow * 2 + 0] + ba0, a1 = A2[hrow * 2 + 1] + ba1;
                    const float g0 = G2[hrow * 2 + 0] + bg0, g1 = G2[hrow * 2 + 1] + bg1;
                    *reinterpret_cast<__half2*>((__half*)g.C + (long long)r * g.ldc + oc) =
                        __floats2half2_rn(a0 * gelu(g0), a1 * gelu(g1));
                }
            }
        }
        return;
    }

    if (QKV) {
        const float d0 = g.qd  ? __ldg(g.qd)  : 1.f;
        const float d1 = g.qd2 ? __ldg(g.qd2) : 1.f;
        const float d2 = g.qd3 ? __ldg(g.qd3) : 1.f;
#pragma unroll
        for (int mf = 0; mf < MF; ++mf) {
            const int r0 = bm + wm * WTM + (mf << 4) + grp;
#pragma unroll
            for (int nf = 0; nf < NF; ++nf) {
                const int c0 = bn + wn * WTN + (nf << 3) + (tg << 1);
                if (c0 >= g.N) continue;
                const int sel = c0 >> 10, col = c0 & 1023;
                __half* Cp = (__half*)(sel == 0 ? g.C : sel == 1 ? g.C2 : g.C3);
                const float qd = sel == 0 ? d0 : sel == 1 ? d1 : d2;
#pragma unroll
                for (int e = 0; e < 4; ++e) {
                    const int r = r0 + ((e >> 1) << 3);
                    const int c = col + (e & 1);
                    if (r < g.M) {
                        float xi = rintf(acc[mf][nf][e] / qd) + 128.f;
                        Cp[(long long)r * 1024 + c] =
                            __float2half_rn(fminf(fmaxf(xi, 0.f), 255.f) - 128.f);
                    }
                }
            }
        }
        return;
    }

    float alpha = g.s0;
    if (g.s1) alpha *= __ldg(g.s1);
    if (g.s2) alpha *= __ldg(g.s2);
    const float qd = g.qd ? __ldg(g.qd) : 1.f;
#pragma unroll
    for (int mf = 0; mf < MF; ++mf) {
        const int r0 = bm + wm * WTM + (mf << 4) + grp;
#pragma unroll
        for (int nf = 0; nf < NF; ++nf) {
            const int c0 = bn + wn * WTN + (nf << 3) + (tg << 1);
#pragma unroll
            for (int e = 0; e < 4; ++e) {
                const int r = r0 + ((e >> 1) << 3);
                const int c = c0 + (e & 1);
                if (r < g.M && c < g.Nstore) {
                    float v = acc[mf][nf][e] * alpha;
                    if (g.bias) v += __ldg(g.bias + c);
                    if (g.res)  v += g.res[(long long)r * g.ldr + c];
                    if (g.qd) {
                        float xi = rintf(v / qd) + 128.f;
                        v = fminf(fmaxf(xi, 0.f), 255.f) - 128.f;
                    }
                    const long long o = (long long)r * g.ldc + c;
                    if (CHALF) ((__half*)g.C)[o] = __float2half_rn(v);
                    else       ((float*)g.C)[o] = v;
                }
            }
        }
    }
}

template<int BN, int WM, int BK, bool CHALF, bool GEGLU, bool QKV>
static void run_h(HArgs a)
{
    constexpr int STG = (128 + BN) * (BK + 8);
    const int smem = 3 * STG * 2;
    cudaFuncSetAttribute(hgemm<BN, WM, BK, CHALF, GEGLU, QKV>,
                         cudaFuncAttributeMaxDynamicSharedMemorySize, smem);
    dim3 grid((a.N + BN - 1) / BN, (a.M + 127) / 128, 1);
    hgemm<BN, WM, BK, CHALF, GEGLU, QKV><<<grid, 256, smem>>>(a);
}
static HArgs ha(const __half* A, const __half* B, void* C,
                int M, int N, int Nstore, int K, int lda, int ldb, int ldc)
{
    HArgs g;
    g.A = A; g.B = B; g.C = C; g.C2 = 0; g.C3 = 0;
    g.M = M; g.N = N; g.Nstore = Nstore; g.K = K;
    g.lda = lda; g.ldb = ldb; g.ldc = ldc; g.ldr = 0;
    g.bias = 0; g.res = 0; g.s1 = 0; g.s2 = 0; g.qd = 0; g.qd2 = 0; g.qd3 = 0;
    g.s0 = 1.f;
    return g;
}

// ---------------- batched 1024x1024 weight transposes (one launch) ----------------
struct WT8 { const float* src[8]; __half* dst[8]; };
__global__ void wtrans8(const __grid_constant__ WT8 jobs)
{
    __shared__ float t[32][33];
    const int j = blockIdx.z;
    const float* in = jobs.src[j];
    __half* out = jobs.dst[j];
    const int n0 = blockIdx.x * 32, k0 = blockIdx.y * 32;
    const int tx = threadIdx.x, ty = threadIdx.y;
#pragma unroll
    for (int i = 0; i < 32; i += 8)
        t[ty + i][tx] = in[(long long)(k0 + ty + i) * 1024 + n0 + tx];
    __syncthreads();
#pragma unroll
    for (int i = 0; i < 32; i += 8)
        out[(long long)(n0 + ty + i) * 1024 + k0 + tx] = __float2half_rn(t[tx][ty + i]);
}
__global__ void wtrans(const float* __restrict__ in, __half* __restrict__ out, int K, int N)
{
    __shared__ float t[32][33];
    const int n0 = blockIdx.x * 32, k0 = blockIdx.y * 32;
    const int tx = threadIdx.x, ty = threadIdx.y;
#pragma unroll
    for (int i = 0; i < 32; i += 8)
        t[ty + i][tx] = in[(long long)(k0 + ty + i) * N + n0 + tx];
    __syncthreads();
#pragma unroll
    for (int i = 0; i < 32; i += 8)
        out[(long long)(n0 + ty + i) * K + k0 + tx] = __float2half_rn(t[tx][ty + i]);
}
__global__ void vtrans(const __half* __restrict__ v, __half* __restrict__ vt, int T, int Tpad)
{
    __shared__ float t[32][33];
    const int bz = blockIdx.z, b = bz >> 4, h = bz & 15;
    const int t0 = blockIdx.x * 32, d0 = blockIdx.y * 32;
    const int tx = threadIdx.x, ty = threadIdx.y;
#pragma unroll
    for (int i = 0; i < 32; i += 8) {
        const int tt = t0 + ty + i;
        t[ty + i][tx] = (tt < T) ? __half2float(v[((long long)b * T + tt) * 1024 + h * 64 + d0 + tx]) : 0.f;
    }
    __syncthreads();
#pragma unroll
    for (int i = 0; i < 32; i += 8) {
        const int tt = t0 + tx;
        if (tt < Tpad)
            vt[(((long long)b * 16 + h) * 64 + d0 + ty + i) * Tpad + tt] = __float2half_rn(t[tx][ty + i]);
    }
}
__global__ void f2h(const float* __restrict__ in, __half* __restrict__ out, int n)
{
    const int i = blockIdx.x * 256 + threadIdx.x;
    if (i < n) out[i] = __float2half_rn(in[i]);
}

// ---------------- layernorm -> half ----------------
__global__ void ln_kernel(const float* __restrict__ x, const float* __restrict__ gm,
                          const float* __restrict__ bt, __half* __restrict__ outH)
{
    __shared__ float red[4];
    const long long row = blockIdx.x;
    const float* xr = x + row * 1024;
    const int t = threadIdx.x;
    float v[8];
    *reinterpret_cast<float4*>(&v[0]) = *reinterpret_cast<const float4*>(xr + t * 8);
    *reinterpret_cast<float4*>(&v[4]) = *reinterpret_cast<const float4*>(xr + t * 8 + 4);
    float s = 0.f;
#pragma unroll
    for (int i = 0; i < 8; ++i) s += v[i];
#pragma unroll
    for (int o = 16; o; o >>= 1) s += __shfl_xor_sync(0xffffffffu, s, o);
    if ((t & 31) == 0) red[t >> 5] = s;
    __syncthreads();
    const float mu = (red[0] + red[1] + red[2] + red[3]) * (1.f / 1024.f);
    __syncthreads();
    float ss = 0.f;
#pragma unroll
    for (int i = 0; i < 8; ++i) { float d = v[i] - mu; ss += d * d; }
#pragma unroll
    for (int o = 16; o; o >>= 1) ss += __shfl_xor_sync(0xffffffffu, ss, o);
    if ((t & 31) == 0) red[t >> 5] = ss;
    __syncthreads();
    const float rs = rsqrtf((red[0] + red[1] + red[2] + red[3]) * (1.f / 1024.f) + 1e-5f);
#pragma unroll
    for (int i = 0; i < 4; ++i) {
        const int c = t * 8 + i * 2;
        *reinterpret_cast<__half2*>(outH + row * 1024 + c) =
            __floats2half2_rn((v[i*2]   - mu) * rs * gm[c]   + bt[c],
                              (v[i*2+1] - mu) * rs * gm[c+1] + bt[c+1]);
    }
}

// ---------------- launcher ----------------
extern "C" void kernel_launch(void* const* d_in, const int* in_sizes, int n_in,
                              void* d_out, int out_size)
{
    (void)in_sizes; (void)n_in; (void)out_size;
    const float* x   = (const float*)d_in[0];
    const float* ctx = (const float*)d_in[1];
    const float *ln1g = (const float*)d_in[2], *ln1b = (const float*)d_in[3];
    const float *ln2g = (const float*)d_in[4], *ln2b = (const float*)d_in[5];
    const float *ln3g = (const float*)d_in[6], *ln3b = (const float*)d_in[7];
    const float *wq1 = (const float*)d_in[8],  *wk1 = (const float*)d_in[9];
    const float *wv1 = (const float*)d_in[10], *wo1 = (const float*)d_in[11];
    const float *bo1 = (const float*)d_in[12];
    const float *wq2 = (const float*)d_in[13], *wk2 = (const float*)d_in[14];
    const float *wv2 = (const float*)d_in[15], *wo2 = (const float*)d_in[16];
    const float *bo2 = (const float*)d_in[17];
    const float *w1 = (const float*)d_in[18], *b1 = (const float*)d_in[19];
    const float *w2 = (const float*)d_in[20], *b2 = (const float*)d_in[21];
    const float *dq1 = (const float*)d_in[22], *dk1 = (const float*)d_in[23];
    const float *dv1 = (const float*)d_in[24], *dw1 = (const float*)d_in[25];
    const float *dq2 = (const float*)d_in[26], *dk2 = (const float*)d_in[27];
    const float *dv2 = (const float*)d_in[28], *dw2 = (const float*)d_in[29];
    float* out = (float*)d_out;

    float *px, *ph, *pq, *pk, *pv, *po, *pvt, *pgg, *pw, *pcs;
    cudaGetSymbolAddress((void**)&px,  g_x);
    cudaGetSymbolAddress((void**)&ph,  g_h);
    cudaGetSymbolAddress((void**)&pq,  g_q);
    cudaGetSymbolAddress((void**)&pk,  g_k);
    cudaGetSymbolAddress((void**)&pv,  g_v);
    cudaGetSymbolAddress((void**)&po,  g_o);
    cudaGetSymbolAddress((void**)&pvt, g_vt);
    cudaGetSymbolAddress((void**)&pgg, g_gg);
    cudaGetSymbolAddress((void**)&pw,  g_w);
    cudaGetSymbolAddress((void**)&pcs, g_cs);

    __half *hh = (__half*)ph;
    __half *hq = (__half*)pq, *hk = (__half*)pk, *hv = (__half*)pv, *hvt = (__half*)pvt;
    __half *hpo = (__half*)po, *hgg = (__half*)pgg;
    __half *hw = (__half*)pw, *chx = (__half*)pcs;

    const long long M1h = 1048576;                 // halfs
    __half *qkv1t = hw;                            // [3072,1024]
    __half *kv2t  = hw + 3*M1h;                    // [2048,1024]
    __half *q2t   = hw + 5*M1h;
    __half *o1t   = hw + 6*M1h, *o2t = hw + 7*M1h;
    __half *w1t   = hw + 8*M1h;                    // [8192,1024]
    __half *w2t   = hw + 16*M1h;                   // [1024,4096]

    dim3 tb(32, 8);
    {
        WT8 j;
        j.src[0] = wq1; j.dst[0] = qkv1t;
        j.src[1] = wk1; j.dst[1] = qkv1t + M1h;
        j.src[2] = wv1; j.dst[2] = qkv1t + 2*M1h;
        j.src[3] = wk2; j.dst[3] = kv2t;
        j.src[4] = wv2; j.dst[4] = kv2t + M1h;
        j.src[5] = wq2; j.dst[5] = q2t;
        j.src[6] = wo1; j.dst[6] = o1t;
        j.src[7] = wo2; j.dst[7] = o2t;
        wtrans8<<<dim3(32,32,8), tb>>>(j);
    }
    wtrans<<<dim3(256,32), tb>>>(w1, w1t, 1024, 8192);
    wtrans<<<dim3(32,128), tb>>>(w2, w2t, 4096, 1024);
    f2h<<<616, 256>>>(ctx, chx, 157696);

    const int FSM = 90112;
    cudaFuncSetAttribute(fattn, cudaFuncAttributeMaxDynamicSharedMemorySize, FSM);

    // ===== self attention =====
    ln_kernel<<<4096, 128>>>(x, ln1g, ln1b, hh);
    { HArgs g = ha(hh, qkv1t, hq, 4096,3072,3072,1024, 1024,1024,1024);
      g.C2 = hk; g.C3 = hv; g.qd = dq1; g.qd2 = dk1; g.qd3 = dv1;
      run_h<128,2,64,true,false,true>(g); }
    vtrans<<<dim3(64,2,32), tb>>>(hv, hvt, 2048, 2048);
    fattn<<<dim3(16,1,32), 256, FSM>>>(hq, hk, hvt, hpo, 2048, 2048, 2048, dq1, dk1, dw1, dv1);
    { HArgs g = ha(hpo, o1t, px, 4096,1024,1024,1024, 1024,1024,1024);
      g.bias = bo1; g.res = x; g.ldr = 1024; run_h<128,2,64,false,false,false>(g); }

    // ===== cross attention =====
    ln_kernel<<<4096, 128>>>(px, ln2g, ln2b, hh);
    { HArgs g = ha(hh, q2t, hq, 4096,1024,1024,1024, 1024,1024,1024);
      g.qd = dq2; run_h<128,2,64,true,false,false>(g); }
    { HArgs g = ha(chx, kv2t, hk, 154,2048,2048,1024, 1024,1024,1024);
      g.C2 = hv; g.qd = dk2; g.qd2 = dv2; run_h<128,2,64,true,false,true>(g); }
    vtrans<<<dim3(3,2,32), tb>>>(hv, hvt, 77, 96);
    fattn<<<dim3(16,1,32), 256, FSM>>>(hq, hk, hvt, hpo, 2048, 77, 96, dq2, dk2, dw2, dv2);
    { HArgs g = ha(hpo, o2t, px, 4096,1024,1024,1024, 1024,1024,1024);
      g.bias = bo2; g.res = px; g.ldr = 1024; run_h<128,2,64,false,false,false>(g); }

    // ===== GEGLU feed-forward (fused FFN1+GEGLU) =====
    ln_kernel<<<4096, 128>>>(px, ln3g, ln3b, hh);
    { HArgs g = ha(hh, w1t, hgg, 4096,8192,8192,1024, 1024,1024,4096);
      g.bias = b1; run_h<128,2,64,true,true,false>(g); }
    { HArgs g = ha(hgg, w2t, out, 4096,1024,1024,4096, 4096,4096,1024);
      g.bias = b2; g.res = px; g.ldr = 1024; run_h<128,2,64,false,false,false>(g); }
}

// round 14
// speedup vs baseline: 1.0303x; 1.0303x over previous
#include <cuda_runtime.h>
#include <cuda_fp16.h>
#include <cstdint>
#include <math.h>

// ---------------- scratch ----------------
__device__ float g_x [4194304];
__device__ float g_h [4194304];   // ln out: half
__device__ float g_q [4194304];   // half codes
__device__ float g_k [4194304];
__device__ float g_v [4194304];
__device__ float g_o [4194304];   // half attn out
__device__ float g_vt[4194304];   // half v^T codes
__device__ float g_gg[16777216];  // half GEGLU out
__device__ float g_w [27262976];  // half weights (reinterpret)
__device__ float g_cs[163840];    // half ctx

// ---------------- helpers ----------------
static __device__ __forceinline__ uint32_t smem_u32(const void* p) {
    uint32_t a;
    asm("{ .reg .u64 t; cvta.to.shared.u64 t, %1; cvt.u32.u64 %0, t; }" : "=r"(a) : "l"(p));
    return a;
}
#define MMAH(d, a, b) \
    asm volatile("mma.sync.aligned.m16n8k16.row.col.f32.f16.f16.f32 " \
        "{%0,%1,%2,%3},{%4,%5,%6,%7},{%8,%9},{%0,%1,%2,%3};" \
        : "+f"((d)[0]), "+f"((d)[1]), "+f"((d)[2]), "+f"((d)[3]) \
        : "r"((a)[0]), "r"((a)[1]), "r"((a)[2]), "r"((a)[3]), "r"((b)[0]), "r"((b)[1]))
#define LDSM4(r0, r1, r2, r3, addr) \
    asm volatile("ldmatrix.sync.aligned.m8n8.x4.shared.b16 {%0,%1,%2,%3}, [%4];" \
        : "=r"(r0), "=r"(r1), "=r"(r2), "=r"(r3) : "r"(addr))
#define CPA(dst, src, sz) \
    asm volatile("cp.async.cg.shared.global [%0], [%1], 16, %2;" :: "r"(dst), "l"(src), "r"(sz))
static __device__ __forceinline__ uint32_t packh2(float a, float b) {
    __half2 h = __floats2half2_rn(a, b);
    return *reinterpret_cast<uint32_t*>(&h);
}
static __device__ __forceinline__ float gelu(float g) {
    return 0.5f * g * (1.f + erff(g * 0.70710678118654752440f));
}

// ================= fused attention (two-pass, max-free softmax) =================
__global__ void __launch_bounds__(256)
fattn(const __half* __restrict__ q, const __half* __restrict__ k,
      const __half* __restrict__ vt, __half* __restrict__ o,
      int Tq, int Tk, int Tkpad,
      const float* __restrict__ dqp, const float* __restrict__ dkp,
      const float* __restrict__ dwp, const float* __restrict__ dvp)
{
    constexpr int QS = 128 * 72, KS = 128 * 72, VS = 64 * 136;
    extern __shared__ __half sh[];
    const uint32_t smb = smem_u32(sh);
    const uint32_t kb_ = smb + QS * 2, vb_ = smb + (QS + 2 * KS) * 2;

    const int tid = threadIdx.x, wid = tid >> 5, lane = tid & 31;
    const int grp = lane >> 2, tg = lane & 3;
    const int lm = lane & 7, lmat = lane >> 3;
    const int bh = blockIdx.z, b = bh >> 4, h = bh & 15;
    const int m0 = blockIdx.x * 128;
    const int nkt = (Tk + 127) >> 7;

    const float alpha = 0.125f * __ldg(dqp) * __ldg(dkp);
    const float dw = __ldg(dwp);
    const float beta = dw * __ldg(dvp);

    const uint32_t qOff = ((uint32_t)((wid * 16 + (lmat & 1) * 8 + lm) * 72 + ((lmat >> 1) << 3))) * 2;
    uint32_t kOff[8], vOff[4];
#pragma unroll
    for (int p = 0; p < 8; ++p)
        kOff[p] = ((uint32_t)((p * 16 + (lmat >> 1) * 8 + lm) * 72 + ((lmat & 1) << 3))) * 2;
#pragma unroll
    for (int p = 0; p < 4; ++p)
        vOff[p] = ((uint32_t)((p * 16 + (lmat >> 1) * 8 + lm) * 136 + ((lmat & 1) << 3))) * 2;

    {
        const __half* qb = q + ((long long)b * Tq + m0) * 1024 + h * 64;
#pragma unroll
        for (int i = 0; i < 4; ++i) {
            const int idx = tid + (i << 8);
            const int r = idx >> 3, c = idx & 7;
            CPA(smb + (uint32_t)(r * 72 + (c << 3)) * 2, qb + (long long)r * 1024 + (c << 3), 16);
        }
    }

    auto loadK = [&](int t, int st) {
        const __half* kbase = k + ((long long)b * Tk) * 1024 + h * 64;
#pragma unroll
        for (int i = 0; i < 4; ++i) {
            const int idx = tid + (i << 8);
            const int r = idx >> 3, c = idx & 7;
            const int key = t * 128 + r;
            const int ok = key < Tk;
            const __half* s = ok ? (kbase + (long long)key * 1024 + (c << 3)) : kbase;
            CPA(kb_ + (uint32_t)(st * KS + r * 72 + (c << 3)) * 2, s, ok ? 16 : 0);
        }
    };
    auto loadV = [&](int t, int st) {
        const __half* vbase = vt + ((long long)bh * 64) * Tkpad;
#pragma unroll
        for (int i = 0; i < 4; ++i) {
            const int idx = tid + (i << 8);
            const int r = idx >> 4, c = idx & 15;
            const int key = t * 128 + (c << 3);
            const int ok = (key + 8) <= Tkpad;
            const __half* s = ok ? (vbase + (long long)r * Tkpad + key) : vbase;
            CPA(vb_ + (uint32_t)(st * VS + r * 136 + (c << 3)) * 2, s, ok ? 16 : 0);
        }
    };

    float sacc[16][4];
    auto computeS = [&](int st) {
#pragma unroll
        for (int nf = 0; nf < 16; ++nf)
#pragma unroll
            for (int e = 0; e < 4; ++e) sacc[nf][e] = 0.f;
        const uint32_t kB = kb_ + (uint32_t)st * KS * 2;
#pragma unroll
        for (int kc = 0; kc < 4; ++kc) {
            const uint32_t kb2 = (uint32_t)(kc << 5);
            uint32_t ah[4];
            LDSM4(ah[0], ah[1], ah[2], ah[3], smb + qOff + kb2);
            uint32_t bf[16][2];
#pragma unroll
            for (int p = 0; p < 8; ++p)
                LDSM4(bf[2*p][0], bf[2*p][1], bf[2*p+1][0], bf[2*p+1][1], kB + kOff[p] + kb2);
#pragma unroll
            for (int nf = 0; nf < 16; ++nf) MMAH(sacc[nf], ah, bf[nf]);
        }
    };

    // ---- pass 1 (single sync per tile) ----
    float psum0 = 0.f, psum1 = 0.f;
    loadK(0, 0);
    asm volatile("cp.async.commit_group;");
    for (int t = 0; t < nkt; ++t) {
        asm volatile("cp.async.wait_group 0;");
        __syncthreads();
        if (t + 1 < nkt) {
            loadK(t + 1, (t + 1) & 1);
            asm volatile("cp.async.commit_group;");
        }
        computeS(t & 1);
        const int cb = t * 128;
#pragma unroll
        for (int nf = 0; nf < 16; ++nf) {
            const int c0 = cb + nf * 8 + (tg << 1);
            if (c0 < Tk)     { psum0 += expf(sacc[nf][0] * alpha); psum1 += expf(sacc[nf][2] * alpha); }
            if (c0 + 1 < Tk) { psum0 += expf(sacc[nf][1] * alpha); psum1 += expf(sacc[nf][3] * alpha); }
        }
    }
    psum0 += __shfl_xor_sync(0xffffffffu, psum0, 1);
    psum0 += __shfl_xor_sync(0xffffffffu, psum0, 2);
    psum1 += __shfl_xor_sync(0xffffffffu, psum1, 1);
    psum1 += __shfl_xor_sync(0xffffffffu, psum1, 2);

    // ---- pass 2 (single sync per tile) ----
    float oacc[8][4];
#pragma unroll
    for (int i = 0; i < 8; ++i)
#pragma unroll
        for (int e = 0; e < 4; ++e) oacc[i][e] = 0.f;

    __syncthreads();          // pass-1 buffers fully consumed before refill
    loadK(0, 0); loadV(0, 0);
    asm volatile("cp.async.commit_group;");
    for (int t = 0; t < nkt; ++t) {
        asm volatile("cp.async.wait_group 0;");
        __syncthreads();
        if (t + 1 < nkt) {
            loadK(t + 1, (t + 1) & 1);
            loadV(t + 1, (t + 1) & 1);
            asm volatile("cp.async.commit_group;");
        }
        computeS(t & 1);
        const uint32_t vB = vb_ + (uint32_t)(t & 1) * VS * 2;
        const int cb = t * 128;
#pragma unroll
        for (int kb = 0; kb < 8; ++kb) {
            uint32_t ah[4];
#pragma unroll
            for (int hf = 0; hf < 2; ++hf) {
                const int nf = 2 * kb + hf;
                const int c0 = cb + nf * 8 + (tg << 1);
                const int ok0 = c0 < Tk, ok1 = (c0 + 1) < Tk;
                float p0 = ok0 ? expf(sacc[nf][0] * alpha) / psum0 : 0.f;
                float p1 = ok1 ? expf(sacc[nf][1] * alpha) / psum0 : 0.f;
                float p2 = ok0 ? expf(sacc[nf][2] * alpha) / psum1 : 0.f;
                float p3 = ok1 ? expf(sacc[nf][3] * alpha) / psum1 : 0.f;
                const float q0 = fminf(fmaxf(rintf(p0 / dw), 0.f), 255.f);
                const float q1 = fminf(fmaxf(rintf(p1 / dw), 0.f), 255.f);
                const float q2 = fminf(fmaxf(rintf(p2 / dw), 0.f), 255.f);
                const float q3 = fminf(fmaxf(rintf(p3 / dw), 0.f), 255.f);
                ah[hf * 2]     = packh2(q0, q1);
                ah[hf * 2 + 1] = packh2(q2, q3);
            }
            const uint32_t kb2 = (uint32_t)(kb << 5);
            uint32_t bf[8][2];
#pragma unroll
            for (int p = 0; p < 4; ++p)
                LDSM4(bf[2*p][0], bf[2*p][1], bf[2*p+1][0], bf[2*p+1][1], vB + vOff[p] + kb2);
#pragma unroll
            for (int nfo = 0; nfo < 8; ++nfo) MMAH(oacc[nfo], ah, bf[nfo]);
        }
    }

    const int row0 = m0 + wid * 16 + grp;
    __half* ob = o + ((long long)b * Tq) * 1024 + h * 64;
#pragma unroll
    for (int nfo = 0; nfo < 8; ++nfo) {
        const int c = nfo * 8 + (tg << 1);
        *reinterpret_cast<__half2*>(ob + (long long)row0 * 1024 + c) =
            __floats2half2_rn(oacc[nfo][0] * beta, oacc[nfo][1] * beta);
        *reinterpret_cast<__half2*>(ob + (long long)(row0 + 8) * 1024 + c) =
            __floats2half2_rn(oacc[nfo][2] * beta, oacc[nfo][3] * beta);
    }
}

// ================= fp16 mma GEMM (2-stage, single sync per chunk) =================
struct HArgs {
    const __half *A, *B; void *C, *C2, *C3;
    int M, N, Nstore, K, lda, ldb, ldc, ldr;
    const float *bias, *res, *s1, *s2, *qd, *qd2, *qd3;
    float s0;
};

static __device__ __forceinline__ int geglu_src(int n) {
    const int gp = n >> 4, r = n & 15;
    return (r < 8) ? (gp * 8 + r) : (4096 + gp * 8 + (r - 8));
}

template<int BN, int WM, int BK, bool CHALF, bool GEGLU, bool QKV>
__global__ void __launch_bounds__(256)
hgemm(const __grid_constant__ HArgs g)
{
    constexpr int WN = 8 / WM, WTM = 128 / WM, WTN = BN / WN;
    constexpr int MF = WTM / 16, NF = WTN / 8;
    constexpr int SB = BK + 8;
    constexpr int AS = 128 * SB, BS = BN * SB;
    constexpr int STG = AS + BS;
    constexpr int KPC = BK / 8;
    constexpr int KK  = BK / 16;

    extern __shared__ __half smh[];
    const uint32_t smb = smem_u32(smh);
    const int tid = threadIdx.x, wid = tid >> 5, lane = tid & 31;
    const int grp = lane >> 2, tg = lane & 3;
    const int lm = lane & 7, lmat = lane >> 3;
    const int wm = wid / WN, wn = wid % WN;

    const int bm = blockIdx.y * 128, bn = blockIdx.x * BN;
    const int nch = g.K / BK;

    uint32_t aOff[MF], bOff[NF / 2];
#pragma unroll
    for (int mf = 0; mf < MF; ++mf)
        aOff[mf] = ((uint32_t)((wm * WTM + mf * 16 + (lmat & 1) * 8 + lm) * SB + ((lmat >> 1) << 3))) * 2;
#pragma unroll
    for (int p = 0; p < NF / 2; ++p)
        bOff[p] = ((uint32_t)((wn * WTN + p * 16 + (lmat >> 1) * 8 + lm) * SB + ((lmat & 1) << 3))) * 2;

    float acc[MF][NF][4];
#pragma unroll
    for (int i = 0; i < MF; ++i)
#pragma unroll
        for (int j = 0; j < NF; ++j)
#pragma unroll
            for (int c = 0; c < 4; ++c) acc[i][j][c] = 0.f;

    auto issue = [&](int ch, int st) {
        const int k0 = ch * BK;
        const uint32_t sa = smb + (uint32_t)st * STG * 2;
#pragma unroll
        for (int i = 0; i < 128 * KPC / 256; ++i) {
            const int idx = tid + (i << 8);
            const int r = idx / KPC, c = idx % KPC;
            const int gr = bm + r, ok = (gr < g.M);
            const __half* s = ok ? (g.A + (long long)gr * g.lda + k0 + (c << 3)) : g.A;
            CPA(sa + (uint32_t)(r * SB + (c << 3)) * 2, s, ok ? 16 : 0);
        }
#pragma unroll
        for (int i = 0; i < BN * KPC / 256; ++i) {
            const int idx = tid + (i << 8);
            const int r = idx / KPC, c = idx % KPC;
            const int gn = bn + r, ok = (gn < g.N);
            const int srow = GEGLU ? geglu_src(gn) : gn;
            const __half* s = ok ? (g.B + (long long)srow * g.ldb + k0 + (c << 3)) : g.B;
            CPA(sa + (uint32_t)(AS + r * SB + (c << 3)) * 2, s, ok ? 16 : 0);
        }
    };

    auto compute = [&](int st) {
        const uint32_t aB = smb + (uint32_t)st * STG * 2;
        const uint32_t bB = aB + (uint32_t)AS * 2;
#pragma unroll
        for (int kk = 0; kk < KK; ++kk) {
            const uint32_t kb2 = (uint32_t)(kk << 5);
            uint32_t bh[NF][2];
#pragma unroll
            for (int p = 0; p < NF / 2; ++p)
                LDSM4(bh[2*p][0], bh[2*p][1], bh[2*p+1][0], bh[2*p+1][1], bB + bOff[p] + kb2);
#pragma unroll
            for (int mf = 0; mf < MF; ++mf) {
                uint32_t ah[4];
                LDSM4(ah[0], ah[1], ah[2], ah[3], aB + aOff[mf] + kb2);
#pragma unroll
                for (int nf = 0; nf < NF; ++nf) MMAH(acc[mf][nf], ah, bh[nf]);
            }
        }
    };

    // 2-stage double buffer, ONE __syncthreads per chunk.
    // At iter ch: sync guarantees all warps finished compute(ch-1) (which read
    // buffer (ch+1)&1), so issuing chunk ch+1 into that buffer is safe.
    issue(0, 0);
    asm volatile("cp.async.commit_group;");
    for (int ch = 0; ch < nch; ++ch) {
        asm volatile("cp.async.wait_group 0;");
        __syncthreads();
        if (ch + 1 < nch) {
            issue(ch + 1, (ch + 1) & 1);
            asm volatile("cp.async.commit_group;");
        }
        compute(ch & 1);
    }

    if (GEGLU) {
#pragma unroll
        for (int mf = 0; mf < MF; ++mf) {
            const int r0 = bm + wm * WTM + (mf << 4) + grp;
#pragma unroll
            for (int p = 0; p < NF / 2; ++p) {
                const int va = bn + wn * WTN + (p << 4) + (tg << 1);
                const int oc = ((va >> 4) << 3) + (va & 7);
                const float ba0 = __ldg(g.bias + oc),        ba1 = __ldg(g.bias + oc + 1);
                const float bg0 = __ldg(g.bias + 4096 + oc), bg1 = __ldg(g.bias + 4096 + oc + 1);
                float* A2 = acc[mf][2 * p];
                float* G2 = acc[mf][2 * p + 1];
#pragma unroll
                for (int hrow = 0; hrow < 2; ++hrow) {
                    const int r = r0 + hrow * 8;
                    const float a0 = A2[hrow * 2 + 0] + ba0, a1 = A2[hrow * 2 + 1] + ba1;
                    const float g0 = G2[hrow * 2 + 0] + bg0, g1 = G2[hrow * 2 + 1] + bg1;
                    *reinterpret_cast<__half2*>((__half*)g.C + (long long)r * g.ldc + oc) =
                        __floats2half2_rn(a0 * gelu(g0), a1 * gelu(g1));
                }
            }
        }
        return;
    }

    if (QKV) {
        const float d0 = g.qd  ? __ldg(g.qd)  : 1.f;
        const float d1 = g.qd2 ? __ldg(g.qd2) : 1.f;
        const float d2 = g.qd3 ? __ldg(g.qd3) : 1.f;
#pragma unroll
        for (int mf = 0; mf < MF; ++mf) {
            const int r0 = bm + wm * WTM + (mf << 4) + grp;
#pragma unroll
            for (int nf = 0; nf < NF; ++nf) {
                const int c0 = bn + wn * WTN + (nf << 3) + (tg << 1);
                if (c0 >= g.N) continue;
                const int sel = c0 >> 10, col = c0 & 1023;
                __half* Cp = (__half*)(sel == 0 ? g.C : sel == 1 ? g.C2 : g.C3);
                const float qd = sel == 0 ? d0 : sel == 1 ? d1 : d2;
#pragma unroll
                for (int e = 0; e < 4; ++e) {
                    const int r = r0 + ((e >> 1) << 3);
                    const int c = col + (e & 1);
                    if (r < g.M) {
                        float xi = rintf(acc[mf][nf][e] / qd) + 128.f;
                        Cp[(long long)r * 1024 + c] =
                            __float2half_rn(fminf(fmaxf(xi, 0.f), 255.f) - 128.f);
                    }
                }
            }
        }
        return;
    }

    float alpha = g.s0;
    if (g.s1) alpha *= __ldg(g.s1);
    if (g.s2) alpha *= __ldg(g.s2);
    const float qd = g.qd ? __ldg(g.qd) : 1.f;
#pragma unroll
    for (int mf = 0; mf < MF; ++mf) {
        const int r0 = bm + wm * WTM + (mf << 4) + grp;
#pragma unroll
        for (int nf = 0; nf < NF; ++nf) {
            const int c0 = bn + wn * WTN + (nf << 3) + (tg << 1);
#pragma unroll
            for (int e = 0; e < 4; ++e) {
                const int r = r0 + ((e >> 1) << 3);
                const int c = c0 + (e & 1);
                if (r < g.M && c < g.Nstore) {
                    float v = acc[mf][nf][e] * alpha;
                    if (g.bias) v += __ldg(g.bias + c);
                    if (g.res)  v += g.res[(long long)r * g.ldr + c];
                    if (g.qd) {
                        float xi = rintf(v / qd) + 128.f;
                        v = fminf(fmaxf(xi, 0.f), 255.f) - 128.f;
                    }
                    const long long o = (long long)r * g.ldc + c;
                    if (CHALF) ((__half*)g.C)[o] = __float2half_rn(v);
                    else       ((float*)g.C)[o] = v;
                }
            }
        }
    }
}

template<int BN, int WM, int BK, bool CHALF, bool GEGLU, bool QKV>
static void run_h(HArgs a)
{
    constexpr int STG = (128 + BN) * (BK + 8);
    const int smem = 2 * STG * 2;
    cudaFuncSetAttribute(hgemm<BN, WM, BK, CHALF, GEGLU, QKV>,
                         cudaFuncAttributeMaxDynamicSharedMemorySize, smem);
    dim3 grid((a.N + BN - 1) / BN, (a.M + 127) / 128, 1);
    hgemm<BN, WM, BK, CHALF, GEGLU, QKV><<<grid, 256, smem>>>(a);
}
static HArgs ha(const __half* A, const __half* B, void* C,
                int M, int N, int Nstore, int K, int lda, int ldb, int ldc)
{
    HArgs g;
    g.A = A; g.B = B; g.C = C; g.C2 = 0; g.C3 = 0;
    g.M = M; g.N = N; g.Nstore = Nstore; g.K = K;
    g.lda = lda; g.ldb = ldb; g.ldc = ldc; g.ldr = 0;
    g.bias = 0; g.res = 0; g.s1 = 0; g.s2 = 0; g.qd = 0; g.qd2 = 0; g.qd3 = 0;
    g.s0 = 1.f;
    return g;
}

// ---------------- batched 1024x1024 weight transposes (one launch) ----------------
struct WT8 { const float* src[8]; __half* dst[8]; };
__global__ void wtrans8(const __grid_constant__ WT8 jobs)
{
    __shared__ float t[32][33];
    const int j = blockIdx.z;
    const float* in = jobs.src[j];
    __half* out = jobs.dst[j];
    const int n0 = blockIdx.x * 32, k0 = blockIdx.y * 32;
    const int tx = threadIdx.x, ty = threadIdx.y;
#pragma unroll
    for (int i = 0; i < 32; i += 8)
        t[ty + i][tx] = in[(long long)(k0 + ty + i) * 1024 + n0 + tx];
    __syncthreads();
#pragma unroll
    for (int i = 0; i < 32; i += 8)
        out[(long long)(n0 + ty + i) * 1024 + k0 + tx] = __float2half_rn(t[tx][ty + i]);
}
__global__ void wtrans(const float* __restrict__ in, __half* __restrict__ out, int K, int N)
{
    __shared__ float t[32][33];
    const int n0 = blockIdx.x * 32, k0 = blockIdx.y * 32;
    const int tx = threadIdx.x, ty = threadIdx.y;
#pragma unroll
    for (int i = 0; i < 32; i += 8)
        t[ty + i][tx] = in[(long long)(k0 + ty + i) * N + n0 + tx];
    __syncthreads();
#pragma unroll
    for (int i = 0; i < 32; i += 8)
        out[(long long)(n0 + ty + i) * K + k0 + tx] = __float2half_rn(t[tx][ty + i]);
}
__global__ void vtrans(const __half* __restrict__ v, __half* __restrict__ vt, int T, int Tpad)
{
    __shared__ float t[32][33];
    const int bz = blockIdx.z, b = bz >> 4, h = bz & 15;
    const int t0 = blockIdx.x * 32, d0 = blockIdx.y * 32;
    const int tx = threadIdx.x, ty = threadIdx.y;
#pragma unroll
    for (int i = 0; i < 32; i += 8) {
        const int tt = t0 + ty + i;
        t[ty + i][tx] = (tt < T) ? __half2float(v[((long long)b * T + tt) * 1024 + h * 64 + d0 + tx]) : 0.f;
    }
    __syncthreads();
#pragma unroll
    for (int i = 0; i < 32; i += 8) {
        const int tt = t0 + tx;
        if (tt < Tpad)
            vt[(((long long)b * 16 + h) * 64 + d0 + ty + i) * Tpad + tt] = __float2half_rn(t[tx][ty + i]);
    }
}
__global__ void f2h(const float* __restrict__ in, __half* __restrict__ out, int n)
{
    const int i = blockIdx.x * 256 + threadIdx.x;
    if (i < n) out[i] = __float2half_rn(in[i]);
}

// ---------------- layernorm -> half ----------------
__global__ void ln_kernel(const float* __restrict__ x, const float* __restrict__ gm,
                          const float* __restrict__ bt, __half* __restrict__ outH)
{
    __shared__ float red[4];
    const long long row = blockIdx.x;
    const float* xr = x + row * 1024;
    const int t = threadIdx.x;
    float v[8];
    *reinterpret_cast<float4*>(&v[0]) = *reinterpret_cast<const float4*>(xr + t * 8);
    *reinterpret_cast<float4*>(&v[4]) = *reinterpret_cast<const float4*>(xr + t * 8 + 4);
    float s = 0.f;
#pragma unroll
    for (int i = 0; i < 8; ++i) s += v[i];
#pragma unroll
    for (int o = 16; o; o >>= 1) s += __shfl_xor_sync(0xffffffffu, s, o);
    if ((t & 31) == 0) red[t >> 5] = s;
    __syncthreads();
    const float mu = (red[0] + red[1] + red[2] + red[3]) * (1.f / 1024.f);
    __syncthreads();
    float ss = 0.f;
#pragma unroll
    for (int i = 0; i < 8; ++i) { float d = v[i] - mu; ss += d * d; }
#pragma unroll
    for (int o = 16; o; o >>= 1) ss += __shfl_xor_sync(0xffffffffu, ss, o);
    if ((t & 31) == 0) red[t >> 5] = ss;
    __syncthreads();
    const float rs = rsqrtf((red[0] + red[1] + red[2] + red[3]) * (1.f / 1024.f) + 1e-5f);
#pragma unroll
    for (int i = 0; i < 4; ++i) {
        const int c = t * 8 + i * 2;
        *reinterpret_cast<__half2*>(outH + row * 1024 + c) =
            __floats2half2_rn((v[i*2]   - mu) * rs * gm[c]   + bt[c],
                              (v[i*2+1] - mu) * rs * gm[c+1] + bt[c+1]);
    }
}

// ---------------- launcher ----------------
extern "C" void kernel_launch(void* const* d_in, const int* in_sizes, int n_in,
                              void* d_out, int out_size)
{
    (void)in_sizes; (void)n_in; (void)out_size;
    const float* x   = (const float*)d_in[0];
    const float* ctx = (const float*)d_in[1];
    const float *ln1g = (const float*)d_in[2], *ln1b = (const float*)d_in[3];
    const float *ln2g = (const float*)d_in[4], *ln2b = (const float*)d_in[5];
    const float *ln3g = (const float*)d_in[6], *ln3b = (const float*)d_in[7];
    const float *wq1 = (const float*)d_in[8],  *wk1 = (const float*)d_in[9];
    const float *wv1 = (const float*)d_in[10], *wo1 = (const float*)d_in[11];
    const float *bo1 = (const float*)d_in[12];
    const float *wq2 = (const float*)d_in[13], *wk2 = (const float*)d_in[14];
    const float *wv2 = (const float*)d_in[15], *wo2 = (const float*)d_in[16];
    const float *bo2 = (const float*)d_in[17];
    const float *w1 = (const float*)d_in[18], *b1 = (const float*)d_in[19];
    const float *w2 = (const float*)d_in[20], *b2 = (const float*)d_in[21];
    const float *dq1 = (const float*)d_in[22], *dk1 = (const float*)d_in[23];
    const float *dv1 = (const float*)d_in[24], *dw1 = (const float*)d_in[25];
    const float *dq2 = (const float*)d_in[26], *dk2 = (const float*)d_in[27];
    const float *dv2 = (const float*)d_in[28], *dw2 = (const float*)d_in[29];
    float* out = (float*)d_out;

    float *px, *ph, *pq, *pk, *pv, *po, *pvt, *pgg, *pw, *pcs;
    cudaGetSymbolAddress((void**)&px,  g_x);
    cudaGetSymbolAddress((void**)&ph,  g_h);
    cudaGetSymbolAddress((void**)&pq,  g_q);
    cudaGetSymbolAddress((void**)&pk,  g_k);
    cudaGetSymbolAddress((void**)&pv,  g_v);
    cudaGetSymbolAddress((void**)&po,  g_o);
    cudaGetSymbolAddress((void**)&pvt, g_vt);
    cudaGetSymbolAddress((void**)&pgg, g_gg);
    cudaGetSymbolAddress((void**)&pw,  g_w);
    cudaGetSymbolAddress((void**)&pcs, g_cs);

    __half *hh = (__half*)ph;
    __half *hq = (__half*)pq, *hk = (__half*)pk, *hv = (__half*)pv, *hvt = (__half*)pvt;
    __half *hpo = (__half*)po, *hgg = (__half*)pgg;
    __half *hw = (__half*)pw, *chx = (__half*)pcs;

    const long long M1h = 1048576;                 // halfs
    __half *qkv1t = hw;                            // [3072,1024]
    __half *kv2t  = hw + 3*M1h;                    // [2048,1024]
    __half *q2t   = hw + 5*M1h;
    __half *o1t   = hw + 6*M1h, *o2t = hw + 7*M1h;
    __half *w1t   = hw + 8*M1h;                    // [8192,1024]
    __half *w2t   = hw + 16*M1h;                   // [1024,4096]

    dim3 tb(32, 8);
    {
        WT8 j;
        j.src[0] = wq1; j.dst[0] = qkv1t;
        j.src[1] = wk1; j.dst[1] = qkv1t + M1h;
        j.src[2] = wv1; j.dst[2] = qkv1t + 2*M1h;
        j.src[3] = wk2; j.dst[3] = kv2t;
        j.src[4] = wv2; j.dst[4] = kv2t + M1h;
        j.src[5] = wq2; j.dst[5] = q2t;
        j.src[6] = wo1; j.dst[6] = o1t;
        j.src[7] = wo2; j.dst[7] = o2t;
        wtrans8<<<dim3(32,32,8), tb>>>(j);
    }
    wtrans<<<dim3(256,32), tb>>>(w1, w1t, 1024, 8192);
    wtrans<<<dim3(32,128), tb>>>(w2, w2t, 4096, 1024);
    f2h<<<616, 256>>>(ctx, chx, 157696);

    const int FSM = 90112;
    cudaFuncSetAttribute(fattn, cudaFuncAttributeMaxDynamicSharedMemorySize, FSM);

    // ===== self attention =====
    ln_kernel<<<4096, 128>>>(x, ln1g, ln1b, hh);
    { HArgs g = ha(hh, qkv1t, hq, 4096,3072,3072,1024, 1024,1024,1024);
      g.C2 = hk; g.C3 = hv; g.qd = dq1; g.qd2 = dk1; g.qd3 = dv1;
      run_h<128,2,64,true,false,true>(g); }
    vtrans<<<dim3(64,2,32), tb>>>(hv, hvt, 2048, 2048);
    fattn<<<dim3(16,1,32), 256, FSM>>>(hq, hk, hvt, hpo, 2048, 2048, 2048, dq1, dk1, dw1, dv1);
    { HArgs g = ha(hpo, o1t, px, 4096,1024,1024,1024, 1024,1024,1024);
      g.bias = bo1; g.res = x; g.ldr = 1024; run_h<128,2,64,false,false,false>(g); }

    // ===== cross attention =====
    ln_kernel<<<4096, 128>>>(px, ln2g, ln2b, hh);
    { HArgs g = ha(hh, q2t, hq, 4096,1024,1024,1024, 1024,1024,1024);
      g.qd = dq2; run_h<128,2,64,true,false,false>(g); }
    { HArgs g = ha(chx, kv2t, hk, 154,2048,2048,1024, 1024,1024,1024);
      g.C2 = hv; g.qd = dk2; g.qd2 = dv2; run_h<128,2,64,true,false,true>(g); }
    vtrans<<<dim3(3,2,32), tb>>>(hv, hvt, 77, 96);
    fattn<<<dim3(16,1,32), 256, FSM>>>(hq, hk, hvt, hpo, 2048, 77, 96, dq2, dk2, dw2, dv2);
    { HArgs g = ha(hpo, o2t, px, 4096,1024,1024,1024, 1024,1024,1024);
      g.bias = bo2; g.res = px; g.ldr = 1024; run_h<128,2,64,false,false,false>(g); }

    // ===== GEGLU feed-forward (fused FFN1+GEGLU) =====
    ln_kernel<<<4096, 128>>>(px, ln3g, ln3b, hh);
    { HArgs g = ha(hh, w1t, hgg, 4096,8192,8192,1024, 1024,1024,4096);
      g.bias = b1; run_h<128,2,64,true,true,false>(g); }
    { HArgs g = ha(hgg, w2t, out, 4096,1024,1024,4096, 4096,4096,1024);
      g.bias = b2; g.res = px; g.ldr = 1024; run_h<128,2,64,false,false,false>(g); }
}

// round 15
// speedup vs baseline: 1.0534x; 1.0224x over previous
#include <cuda_runtime.h>
#include <cuda_fp16.h>
#include <cstdint>
#include <math.h>

// ---------------- scratch ----------------
__device__ float g_x [4194304];
__device__ float g_h [4194304];   // ln out: half
__device__ float g_q [4194304];   // half codes
__device__ float g_k [4194304];
__device__ float g_v [4194304];
__device__ float g_o [4194304];   // half attn out
__device__ float g_vt[4194304];   // half v^T codes
__device__ float g_gg[16777216];  // half GEGLU out
__device__ float g_w [27262976];  // half weights (reinterpret)
__device__ float g_cs[163840];    // half ctx

// ---------------- helpers ----------------
static __device__ __forceinline__ uint32_t smem_u32(const void* p) {
    uint32_t a;
    asm("{ .reg .u64 t; cvta.to.shared.u64 t, %1; cvt.u32.u64 %0, t; }" : "=r"(a) : "l"(p));
    return a;
}
#define MMAH(d, a, b) \
    asm volatile("mma.sync.aligned.m16n8k16.row.col.f32.f16.f16.f32 " \
        "{%0,%1,%2,%3},{%4,%5,%6,%7},{%8,%9},{%0,%1,%2,%3};" \
        : "+f"((d)[0]), "+f"((d)[1]), "+f"((d)[2]), "+f"((d)[3]) \
        : "r"((a)[0]), "r"((a)[1]), "r"((a)[2]), "r"((a)[3]), "r"((b)[0]), "r"((b)[1]))
#define LDSM4(r0, r1, r2, r3, addr) \
    asm volatile("ldmatrix.sync.aligned.m8n8.x4.shared.b16 {%0,%1,%2,%3}, [%4];" \
        : "=r"(r0), "=r"(r1), "=r"(r2), "=r"(r3) : "r"(addr))
#define CPA(dst, src, sz) \
    asm volatile("cp.async.cg.shared.global [%0], [%1], 16, %2;" :: "r"(dst), "l"(src), "r"(sz))
static __device__ __forceinline__ uint32_t packh2(float a, float b) {
    __half2 h = __floats2half2_rn(a, b);
    return *reinterpret_cast<uint32_t*>(&h);
}
static __device__ __forceinline__ float gelu(float g) {
    return 0.5f * g * (1.f + erff(g * 0.70710678118654752440f));
}

// ================= fused attention (two-pass, max-free softmax) =================
__global__ void __launch_bounds__(256)
fattn(const __half* __restrict__ q, const __half* __restrict__ k,
      const __half* __restrict__ vt, __half* __restrict__ o,
      int Tq, int Tk, int Tkpad,
      const float* __restrict__ dqp, const float* __restrict__ dkp,
      const float* __restrict__ dwp, const float* __restrict__ dvp)
{
    constexpr int QS = 128 * 72, KS = 128 * 72, VS = 64 * 136;
    extern __shared__ __half sh[];
    const uint32_t smb = smem_u32(sh);
    const uint32_t kb_ = smb + QS * 2, vb_ = smb + (QS + 2 * KS) * 2;

    const int tid = threadIdx.x, wid = tid >> 5, lane = tid & 31;
    const int grp = lane >> 2, tg = lane & 3;
    const int lm = lane & 7, lmat = lane >> 3;
    const int bh = blockIdx.z, b = bh >> 4, h = bh & 15;
    const int m0 = blockIdx.x * 128;
    const int nkt = (Tk + 127) >> 7;

    const float alpha = 0.125f * __ldg(dqp) * __ldg(dkp);
    const float dw = __ldg(dwp);
    const float beta = dw * __ldg(dvp);

    const uint32_t qOff = ((uint32_t)((wid * 16 + (lmat & 1) * 8 + lm) * 72 + ((lmat >> 1) << 3))) * 2;
    uint32_t kOff[8], vOff[4];
#pragma unroll
    for (int p = 0; p < 8; ++p)
        kOff[p] = ((uint32_t)((p * 16 + (lmat >> 1) * 8 + lm) * 72 + ((lmat & 1) << 3))) * 2;
#pragma unroll
    for (int p = 0; p < 4; ++p)
        vOff[p] = ((uint32_t)((p * 16 + (lmat >> 1) * 8 + lm) * 136 + ((lmat & 1) << 3))) * 2;

    {
        const __half* qb = q + ((long long)b * Tq + m0) * 1024 + h * 64;
#pragma unroll
        for (int i = 0; i < 4; ++i) {
            const int idx = tid + (i << 8);
            const int r = idx >> 3, c = idx & 7;
            CPA(smb + (uint32_t)(r * 72 + (c << 3)) * 2, qb + (long long)r * 1024 + (c << 3), 16);
        }
    }

    auto loadK = [&](int t, int st) {
        const __half* kbase = k + ((long long)b * Tk) * 1024 + h * 64;
#pragma unroll
        for (int i = 0; i < 4; ++i) {
            const int idx = tid + (i << 8);
            const int r = idx >> 3, c = idx & 7;
            const int key = t * 128 + r;
            const int ok = key < Tk;
            const __half* s = ok ? (kbase + (long long)key * 1024 + (c << 3)) : kbase;
            CPA(kb_ + (uint32_t)(st * KS + r * 72 + (c << 3)) * 2, s, ok ? 16 : 0);
        }
    };
    auto loadV = [&](int t, int st) {
        const __half* vbase = vt + ((long long)bh * 64) * Tkpad;
#pragma unroll
        for (int i = 0; i < 4; ++i) {
            const int idx = tid + (i << 8);
            const int r = idx >> 4, c = idx & 15;
            const int key = t * 128 + (c << 3);
            const int ok = (key + 8) <= Tkpad;
            const __half* s = ok ? (vbase + (long long)r * Tkpad + key) : vbase;
            CPA(vb_ + (uint32_t)(st * VS + r * 136 + (c << 3)) * 2, s, ok ? 16 : 0);
        }
    };

    float sacc[16][4];
    auto computeS = [&](int st) {
#pragma unroll
        for (int nf = 0; nf < 16; ++nf)
#pragma unroll
            for (int e = 0; e < 4; ++e) sacc[nf][e] = 0.f;
        const uint32_t kB = kb_ + (uint32_t)st * KS * 2;
#pragma unroll
        for (int kc = 0; kc < 4; ++kc) {
            const uint32_t kb2 = (uint32_t)(kc << 5);
            uint32_t ah[4];
            LDSM4(ah[0], ah[1], ah[2], ah[3], smb + qOff + kb2);
            uint32_t bf[16][2];
#pragma unroll
            for (int p = 0; p < 8; ++p)
                LDSM4(bf[2*p][0], bf[2*p][1], bf[2*p+1][0], bf[2*p+1][1], kB + kOff[p] + kb2);
#pragma unroll
            for (int nf = 0; nf < 16; ++nf) MMAH(sacc[nf], ah, bf[nf]);
        }
    };

    // ---- pass 1 (single sync per tile) ----
    float psum0 = 0.f, psum1 = 0.f;
    loadK(0, 0);
    asm volatile("cp.async.commit_group;");
    for (int t = 0; t < nkt; ++t) {
        asm volatile("cp.async.wait_group 0;");
        __syncthreads();
        if (t + 1 < nkt) {
            loadK(t + 1, (t + 1) & 1);
            asm volatile("cp.async.commit_group;");
        }
        computeS(t & 1);
        const int cb = t * 128;
#pragma unroll
        for (int nf = 0; nf < 16; ++nf) {
            const int c0 = cb + nf * 8 + (tg << 1);
            if (c0 < Tk)     { psum0 += expf(sacc[nf][0] * alpha); psum1 += expf(sacc[nf][2] * alpha); }
            if (c0 + 1 < Tk) { psum0 += expf(sacc[nf][1] * alpha); psum1 += expf(sacc[nf][3] * alpha); }
        }
    }
    psum0 += __shfl_xor_sync(0xffffffffu, psum0, 1);
    psum0 += __shfl_xor_sync(0xffffffffu, psum0, 2);
    psum1 += __shfl_xor_sync(0xffffffffu, psum1, 1);
    psum1 += __shfl_xor_sync(0xffffffffu, psum1, 2);

    // ---- pass 2 (single sync per tile) ----
    float oacc[8][4];
#pragma unroll
    for (int i = 0; i < 8; ++i)
#pragma unroll
        for (int e = 0; e < 4; ++e) oacc[i][e] = 0.f;

    __syncthreads();
    loadK(0, 0); loadV(0, 0);
    asm volatile("cp.async.commit_group;");
    for (int t = 0; t < nkt; ++t) {
        asm volatile("cp.async.wait_group 0;");
        __syncthreads();
        if (t + 1 < nkt) {
            loadK(t + 1, (t + 1) & 1);
            loadV(t + 1, (t + 1) & 1);
            asm volatile("cp.async.commit_group;");
        }
        computeS(t & 1);
        const uint32_t vB = vb_ + (uint32_t)(t & 1) * VS * 2;
        const int cb = t * 128;
#pragma unroll
        for (int kb = 0; kb < 8; ++kb) {
            uint32_t ah[4];
#pragma unroll
            for (int hf = 0; hf < 2; ++hf) {
                const int nf = 2 * kb + hf;
                const int c0 = cb + nf * 8 + (tg << 1);
                const int ok0 = c0 < Tk, ok1 = (c0 + 1) < Tk;
                float p0 = ok0 ? expf(sacc[nf][0] * alpha) / psum0 : 0.f;
                float p1 = ok1 ? expf(sacc[nf][1] * alpha) / psum0 : 0.f;
                float p2 = ok0 ? expf(sacc[nf][2] * alpha) / psum1 : 0.f;
                float p3 = ok1 ? expf(sacc[nf][3] * alpha) / psum1 : 0.f;
                const float q0 = fminf(fmaxf(rintf(p0 / dw), 0.f), 255.f);
                const float q1 = fminf(fmaxf(rintf(p1 / dw), 0.f), 255.f);
                const float q2 = fminf(fmaxf(rintf(p2 / dw), 0.f), 255.f);
                const float q3 = fminf(fmaxf(rintf(p3 / dw), 0.f), 255.f);
                ah[hf * 2]     = packh2(q0, q1);
                ah[hf * 2 + 1] = packh2(q2, q3);
            }
            const uint32_t kb2 = (uint32_t)(kb << 5);
            uint32_t bf[8][2];
#pragma unroll
            for (int p = 0; p < 4; ++p)
                LDSM4(bf[2*p][0], bf[2*p][1], bf[2*p+1][0], bf[2*p+1][1], vB + vOff[p] + kb2);
#pragma unroll
            for (int nfo = 0; nfo < 8; ++nfo) MMAH(oacc[nfo], ah, bf[nfo]);
        }
    }

    const int row0 = m0 + wid * 16 + grp;
    __half* ob = o + ((long long)b * Tq) * 1024 + h * 64;
#pragma unroll
    for (int nfo = 0; nfo < 8; ++nfo) {
        const int c = nfo * 8 + (tg << 1);
        *reinterpret_cast<__half2*>(ob + (long long)row0 * 1024 + c) =
            __floats2half2_rn(oacc[nfo][0] * beta, oacc[nfo][1] * beta);
        *reinterpret_cast<__half2*>(ob + (long long)(row0 + 8) * 1024 + c) =
            __floats2half2_rn(oacc[nfo][2] * beta, oacc[nfo][3] * beta);
    }
}

// ================= fp16 mma GEMM (2-stage, single sync per chunk) =================
struct HArgs {
    const __half *A, *B; void *C, *C2, *C3;
    int M, N, Nstore, K, lda, ldb, ldc, ldr;
    const float *bias, *res, *s1, *s2, *qd, *qd2, *qd3;
    float s0;
};

static __device__ __forceinline__ int geglu_src(int n) {
    const int gp = n >> 4, r = n & 15;
    return (r < 8) ? (gp * 8 + r) : (4096 + gp * 8 + (r - 8));
}

template<int BN, int WM, int BK, bool CHALF, bool GEGLU, bool QKV>
__global__ void __launch_bounds__(256, 2)
hgemm(const __grid_constant__ HArgs g)
{
    constexpr int WN = 8 / WM, WTM = 128 / WM, WTN = BN / WN;
    constexpr int MF = WTM / 16, NF = WTN / 8;
    constexpr int SB = BK + 8;
    constexpr int AS = 128 * SB, BS = BN * SB;
    constexpr int STG = AS + BS;
    constexpr int KPC = BK / 8;
    constexpr int KK  = BK / 16;

    extern __shared__ __half smh[];
    const uint32_t smb = smem_u32(smh);
    const int tid = threadIdx.x, wid = tid >> 5, lane = tid & 31;
    const int grp = lane >> 2, tg = lane & 3;
    const int lm = lane & 7, lmat = lane >> 3;
    const int wm = wid / WN, wn = wid % WN;

    const int bm = blockIdx.y * 128, bn = blockIdx.x * BN;
    const int nch = g.K / BK;

    uint32_t aOff[MF], bOff[NF / 2];
#pragma unroll
    for (int mf = 0; mf < MF; ++mf)
        aOff[mf] = ((uint32_t)((wm * WTM + mf * 16 + (lmat & 1) * 8 + lm) * SB + ((lmat >> 1) << 3))) * 2;
#pragma unroll
    for (int p = 0; p < NF / 2; ++p)
        bOff[p] = ((uint32_t)((wn * WTN + p * 16 + (lmat >> 1) * 8 + lm) * SB + ((lmat & 1) << 3))) * 2;

    float acc[MF][NF][4];
#pragma unroll
    for (int i = 0; i < MF; ++i)
#pragma unroll
        for (int j = 0; j < NF; ++j)
#pragma unroll
            for (int c = 0; c < 4; ++c) acc[i][j][c] = 0.f;

    auto issue = [&](int ch, int st) {
        const int k0 = ch * BK;
        const uint32_t sa = smb + (uint32_t)st * STG * 2;
#pragma unroll
        for (int i = 0; i < 128 * KPC / 256; ++i) {
            const int idx = tid + (i << 8);
            const int r = idx / KPC, c = idx % KPC;
            const int gr = bm + r, ok = (gr < g.M);
            const __half* s = ok ? (g.A + (long long)gr * g.lda + k0 + (c << 3)) : g.A;
            CPA(sa + (uint32_t)(r * SB + (c << 3)) * 2, s, ok ? 16 : 0);
        }
#pragma unroll
        for (int i = 0; i < BN * KPC / 256; ++i) {
            const int idx = tid + (i << 8);
            const int r = idx / KPC, c = idx % KPC;
            const int gn = bn + r, ok = (gn < g.N);
            const int srow = GEGLU ? geglu_src(gn) : gn;
            const __half* s = ok ? (g.B + (long long)srow * g.ldb + k0 + (c << 3)) : g.B;
            CPA(sa + (uint32_t)(AS + r * SB + (c << 3)) * 2, s, ok ? 16 : 0);
        }
    };

    auto compute = [&](int st) {
        const uint32_t aB = smb + (uint32_t)st * STG * 2;
        const uint32_t bB = aB + (uint32_t)AS * 2;
#pragma unroll
        for (int kk = 0; kk < KK; ++kk) {
            const uint32_t kb2 = (uint32_t)(kk << 5);
            uint32_t bh[NF][2];
#pragma unroll
            for (int p = 0; p < NF / 2; ++p)
                LDSM4(bh[2*p][0], bh[2*p][1], bh[2*p+1][0], bh[2*p+1][1], bB + bOff[p] + kb2);
#pragma unroll
            for (int mf = 0; mf < MF; ++mf) {
                uint32_t ah[4];
                LDSM4(ah[0], ah[1], ah[2], ah[3], aB + aOff[mf] + kb2);
#pragma unroll
                for (int nf = 0; nf < NF; ++nf) MMAH(acc[mf][nf], ah, bh[nf]);
            }
        }
    };

    issue(0, 0);
    asm volatile("cp.async.commit_group;");
    for (int ch = 0; ch < nch; ++ch) {
        asm volatile("cp.async.wait_group 0;");
        __syncthreads();
        if (ch + 1 < nch) {
            issue(ch + 1, (ch + 1) & 1);
            asm volatile("cp.async.commit_group;");
        }
        compute(ch & 1);
    }

    if (GEGLU) {
#pragma unroll
        for (int mf = 0; mf < MF; ++mf) {
            const int r0 = bm + wm * WTM + (mf << 4) + grp;
#pragma unroll
            for (int p = 0; p < NF / 2; ++p) {
                const int va = bn + wn * WTN + (p << 4) + (tg << 1);
                const int oc = ((va >> 4) << 3) + (va & 7);
                const float ba0 = __ldg(g.bias + oc),        ba1 = __ldg(g.bias + oc + 1);
                const float bg0 = __ldg(g.bias + 4096 + oc), bg1 = __ldg(g.bias + 4096 + oc + 1);
                float* A2 = acc[mf][2 * p];
                float* G2 = acc[mf][2 * p + 1];
#pragma unroll
                for (int hrow = 0; hrow < 2; ++hrow) {
                    const int r = r0 + hrow * 8;
                    const float a0 = A2[hrow * 2 + 0] + ba0, a1 = A2[hrow * 2 + 1] + ba1;
                    const float g0 = G2[hrow * 2 + 0] + bg0, g1 = G2[hrow * 2 + 1] + bg1;
                    *reinterpret_cast<__half2*>((__half*)g.C + (long long)r * g.ldc + oc) =
                        __floats2half2_rn(a0 * gelu(g0), a1 * gelu(g1));
                }
            }
        }
        return;
    }

    if (QKV) {
        const float d0 = g.qd  ? __ldg(g.qd)  : 1.f;
        const float d1 = g.qd2 ? __ldg(g.qd2) : 1.f;
        const float d2 = g.qd3 ? __ldg(g.qd3) : 1.f;
#pragma unroll
        for (int mf = 0; mf < MF; ++mf) {
            const int r0 = bm + wm * WTM + (mf << 4) + grp;
#pragma unroll
            for (int nf = 0; nf < NF; ++nf) {
                const int c0 = bn + wn * WTN + (nf << 3) + (tg << 1);
                if (c0 >= g.N) continue;
                const int sel = c0 >> 10, col = c0 & 1023;
                __half* Cp = (__half*)(sel == 0 ? g.C : sel == 1 ? g.C2 : g.C3);
                const float qd = sel == 0 ? d0 : sel == 1 ? d1 : d2;
#pragma unroll
                for (int hrow = 0; hrow < 2; ++hrow) {
                    const int r = r0 + hrow * 8;
                    if (r < g.M) {
                        float x0 = fminf(fmaxf(rintf(acc[mf][nf][hrow*2+0] / qd) + 128.f, 0.f), 255.f) - 128.f;
                        float x1 = fminf(fmaxf(rintf(acc[mf][nf][hrow*2+1] / qd) + 128.f, 0.f), 255.f) - 128.f;
                        *reinterpret_cast<__half2*>(Cp + (long long)r * 1024 + col) =
                            __floats2half2_rn(x0, x1);
                    }
                }
            }
        }
        return;
    }

    float alpha = g.s0;
    if (g.s1) alpha *= __ldg(g.s1);
    if (g.s2) alpha *= __ldg(g.s2);
    const float qd = g.qd ? __ldg(g.qd) : 1.f;
#pragma unroll
    for (int mf = 0; mf < MF; ++mf) {
        const int r0 = bm + wm * WTM + (mf << 4) + grp;
#pragma unroll
        for (int nf = 0; nf < NF; ++nf) {
            const int c0 = bn + wn * WTN + (nf << 3) + (tg << 1);
            if (c0 >= g.Nstore) continue;
#pragma unroll
            for (int hrow = 0; hrow < 2; ++hrow) {
                const int r = r0 + hrow * 8;
                if (r >= g.M) continue;
                float v0 = acc[mf][nf][hrow*2+0] * alpha;
                float v1 = acc[mf][nf][hrow*2+1] * alpha;
                if (g.bias) { v0 += __ldg(g.bias + c0); v1 += __ldg(g.bias + c0 + 1); }
                if (g.res) {
                    v0 += g.res[(long long)r * g.ldr + c0];
                    v1 += g.res[(long long)r * g.ldr + c0 + 1];
                }
                if (g.qd) {
                    v0 = fminf(fmaxf(rintf(v0 / qd) + 128.f, 0.f), 255.f) - 128.f;
                    v1 = fminf(fmaxf(rintf(v1 / qd) + 128.f, 0.f), 255.f) - 128.f;
                }
                if (CHALF) {
                    *reinterpret_cast<__half2*>((__half*)g.C + (long long)r * g.ldc + c0) =
                        __floats2half2_rn(v0, v1);
                } else {
                    float* Cp = (float*)g.C + (long long)r * g.ldc + c0;
                    Cp[0] = v0; Cp[1] = v1;
                }
            }
        }
    }
}

template<int BN, int WM, int BK, bool CHALF, bool GEGLU, bool QKV>
static void run_h(HArgs a)
{
    constexpr int STG = (128 + BN) * (BK + 8);
    const int smem = 2 * STG * 2;
    cudaFuncSetAttribute(hgemm<BN, WM, BK, CHALF, GEGLU, QKV>,
                         cudaFuncAttributeMaxDynamicSharedMemorySize, smem);
    dim3 grid((a.N + BN - 1) / BN, (a.M + 127) / 128, 1);
    hgemm<BN, WM, BK, CHALF, GEGLU, QKV><<<grid, 256, smem>>>(a);
}
static HArgs ha(const __half* A, const __half* B, void* C,
                int M, int N, int Nstore, int K, int lda, int ldb, int ldc)
{
    HArgs g;
    g.A = A; g.B = B; g.C = C; g.C2 = 0; g.C3 = 0;
    g.M = M; g.N = N; g.Nstore = Nstore; g.K = K;
    g.lda = lda; g.ldb = ldb; g.ldc = ldc; g.ldr = 0;
    g.bias = 0; g.res = 0; g.s1 = 0; g.s2 = 0; g.qd = 0; g.qd2 = 0; g.qd3 = 0;
    g.s0 = 1.f;
    return g;
}

// ---------------- batched 1024x1024 weight transposes (one launch) ----------------
struct WT8 { const float* src[8]; __half* dst[8]; };
__global__ void wtrans8(const __grid_constant__ WT8 jobs)
{
    __shared__ float t[32][33];
    const int j = blockIdx.z;
    const float* in = jobs.src[j];
    __half* out = jobs.dst[j];
    const int n0 = blockIdx.x * 32, k0 = blockIdx.y * 32;
    const int tx = threadIdx.x, ty = threadIdx.y;
#pragma unroll
    for (int i = 0; i < 32; i += 8)
        t[ty + i][tx] = in[(long long)(k0 + ty + i) * 1024 + n0 + tx];
    __syncthreads();
#pragma unroll
    for (int i = 0; i < 32; i += 8)
        out[(long long)(n0 + ty + i) * 1024 + k0 + tx] = __float2half_rn(t[tx][ty + i]);
}
__global__ void wtrans(const float* __restrict__ in, __half* __restrict__ out, int K, int N)
{
    __shared__ float t[32][33];
    const int n0 = blockIdx.x * 32, k0 = blockIdx.y * 32;
    const int tx = threadIdx.x, ty = threadIdx.y;
#pragma unroll
    for (int i = 0; i < 32; i += 8)
        t[ty + i][tx] = in[(long long)(k0 + ty + i) * N + n0 + tx];
    __syncthreads();
#pragma unroll
    for (int i = 0; i < 32; i += 8)
        out[(long long)(n0 + ty + i) * K + k0 + tx] = __float2half_rn(t[tx][ty + i]);
}
__global__ void vtrans(const __half* __restrict__ v, __half* __restrict__ vt, int T, int Tpad)
{
    __shared__ float t[32][33];
    const int bz = blockIdx.z, b = bz >> 4, h = bz & 15;
    const int t0 = blockIdx.x * 32, d0 = blockIdx.y * 32;
    const int tx = threadIdx.x, ty = threadIdx.y;
#pragma unroll
    for (int i = 0; i < 32; i += 8) {
        const int tt = t0 + ty + i;
        t[ty + i][tx] = (tt < T) ? __half2float(v[((long long)b * T + tt) * 1024 + h * 64 + d0 + tx]) : 0.f;
    }
    __syncthreads();
#pragma unroll
    for (int i = 0; i < 32; i += 8) {
        const int tt = t0 + tx;
        if (tt < Tpad)
            vt[(((long long)b * 16 + h) * 64 + d0 + ty + i) * Tpad + tt] = __float2half_rn(t[tx][ty + i]);
    }
}
__global__ void f2h(const float* __restrict__ in, __half* __restrict__ out, int n4)
{
    const int i = blockIdx.x * 256 + threadIdx.x;
    if (i < n4) {
        const float4 v = *reinterpret_cast<const float4*>(in + i * 4);
        __half2* op = reinterpret_cast<__half2*>(out + i * 4);
        op[0] = __floats2half2_rn(v.x, v.y);
        op[1] = __floats2half2_rn(v.z, v.w);
    }
}

// ---------------- layernorm -> half ----------------
__global__ void ln_kernel(const float* __restrict__ x, const float* __restrict__ gm,
                          const float* __restrict__ bt, __half* __restrict__ outH)
{
    __shared__ float red[4];
    const long long row = blockIdx.x;
    const float* xr = x + row * 1024;
    const int t = threadIdx.x;
    float v[8];
    *reinterpret_cast<float4*>(&v[0]) = *reinterpret_cast<const float4*>(xr + t * 8);
    *reinterpret_cast<float4*>(&v[4]) = *reinterpret_cast<const float4*>(xr + t * 8 + 4);
    float s = 0.f;
#pragma unroll
    for (int i = 0; i < 8; ++i) s += v[i];
#pragma unroll
    for (int o = 16; o; o >>= 1) s += __shfl_xor_sync(0xffffffffu, s, o);
    if ((t & 31) == 0) red[t >> 5] = s;
    __syncthreads();
    const float mu = (red[0] + red[1] + red[2] + red[3]) * (1.f / 1024.f);
    __syncthreads();
    float ss = 0.f;
#pragma unroll
    for (int i = 0; i < 8; ++i) { float d = v[i] - mu; ss += d * d; }
#pragma unroll
    for (int o = 16; o; o >>= 1) ss += __shfl_xor_sync(0xffffffffu, ss, o);
    if ((t & 31) == 0) red[t >> 5] = ss;
    __syncthreads();
    const float rs = rsqrtf((red[0] + red[1] + red[2] + red[3]) * (1.f / 1024.f) + 1e-5f);
#pragma unroll
    for (int i = 0; i < 4; ++i) {
        const int c = t * 8 + i * 2;
        *reinterpret_cast<__half2*>(outH + row * 1024 + c) =
            __floats2half2_rn((v[i*2]   - mu) * rs * gm[c]   + bt[c],
                              (v[i*2+1] - mu) * rs * gm[c+1] + bt[c+1]);
    }
}

// ---------------- launcher ----------------
extern "C" void kernel_launch(void* const* d_in, const int* in_sizes, int n_in,
                              void* d_out, int out_size)
{
    (void)in_sizes; (void)n_in; (void)out_size;
    const float* x   = (const float*)d_in[0];
    const float* ctx = (const float*)d_in[1];
    const float *ln1g = (const float*)d_in[2], *ln1b = (const float*)d_in[3];
    const float *ln2g = (const float*)d_in[4], *ln2b = (const float*)d_in[5];
    const float *ln3g = (const float*)d_in[6], *ln3b = (const float*)d_in[7];
    const float *wq1 = (const float*)d_in[8],  *wk1 = (const float*)d_in[9];
    const float *wv1 = (const float*)d_in[10], *wo1 = (const float*)d_in[11];
    const float *bo1 = (const float*)d_in[12];
    const float *wq2 = (const float*)d_in[13], *wk2 = (const float*)d_in[14];
    const float *wv2 = (const float*)d_in[15], *wo2 = (const float*)d_in[16];
    const float *bo2 = (const float*)d_in[17];
    const float *w1 = (const float*)d_in[18], *b1 = (const float*)d_in[19];
    const float *w2 = (const float*)d_in[20], *b2 = (const float*)d_in[21];
    const float *dq1 = (const float*)d_in[22], *dk1 = (const float*)d_in[23];
    const float *dv1 = (const float*)d_in[24], *dw1 = (const float*)d_in[25];
    const float *dq2 = (const float*)d_in[26], *dk2 = (const float*)d_in[27];
    const float *dv2 = (const float*)d_in[28], *dw2 = (const float*)d_in[29];
    float* out = (float*)d_out;

    float *px, *ph, *pq, *pk, *pv, *po, *pvt, *pgg, *pw, *pcs;
    cudaGetSymbolAddress((void**)&px,  g_x);
    cudaGetSymbolAddress((void**)&ph,  g_h);
    cudaGetSymbolAddress((void**)&pq,  g_q);
    cudaGetSymbolAddress((void**)&pk,  g_k);
    cudaGetSymbolAddress((void**)&pv,  g_v);
    cudaGetSymbolAddress((void**)&po,  g_o);
    cudaGetSymbolAddress((void**)&pvt, g_vt);
    cudaGetSymbolAddress((void**)&pgg, g_gg);
    cudaGetSymbolAddress((void**)&pw,  g_w);
    cudaGetSymbolAddress((void**)&pcs, g_cs);

    __half *hh = (__half*)ph;
    __half *hq = (__half*)pq, *hk = (__half*)pk, *hv = (__half*)pv, *hvt = (__half*)pvt;
    __half *hpo = (__half*)po, *hgg = (__half*)pgg;
    __half *hw = (__half*)pw, *chx = (__half*)pcs;

    const long long M1h = 1048576;                 // halfs
    __half *qkv1t = hw;                            // [3072,1024]
    __half *kv2t  = hw + 3*M1h;                    // [2048,1024]
    __half *q2t   = hw + 5*M1h;
    __half *o1t   = hw + 6*M1h, *o2t = hw + 7*M1h;
    __half *w1t   = hw + 8*M1h;                    // [8192,1024]
    __half *w2t   = hw + 16*M1h;                   // [1024,4096]

    dim3 tb(32, 8);
    {
        WT8 j;
        j.src[0] = wq1; j.dst[0] = qkv1t;
        j.src[1] = wk1; j.dst[1] = qkv1t + M1h;
        j.src[2] = wv1; j.dst[2] = qkv1t + 2*M1h;
        j.src[3] = wk2; j.dst[3] = kv2t;
        j.src[4] = wv2; j.dst[4] = kv2t + M1h;
        j.src[5] = wq2; j.dst[5] = q2t;
        j.src[6] = wo1; j.dst[6] = o1t;
        j.src[7] = wo2; j.dst[7] = o2t;
        wtrans8<<<dim3(32,32,8), tb>>>(j);
    }
    wtrans<<<dim3(256,32), tb>>>(w1, w1t, 1024, 8192);
    wtrans<<<dim3(32,128), tb>>>(w2, w2t, 4096, 1024);
    f2h<<<154, 256>>>(ctx, chx, 39424);

    const int FSM = 90112;
    cudaFuncSetAttribute(fattn, cudaFuncAttributeMaxDynamicSharedMemorySize, FSM);

    // ===== self attention =====
    ln_kernel<<<4096, 128>>>(x, ln1g, ln1b, hh);
    { HArgs g = ha(hh, qkv1t, hq, 4096,3072,3072,1024, 1024,1024,1024);
      g.C2 = hk; g.C3 = hv; g.qd = dq1; g.qd2 = dk1; g.qd3 = dv1;
      run_h<128,2,64,true,false,true>(g); }
    vtrans<<<dim3(64,2,32), tb>>>(hv, hvt, 2048, 2048);
    fattn<<<dim3(16,1,32), 256, FSM>>>(hq, hk, hvt, hpo, 2048, 2048, 2048, dq1, dk1, dw1, dv1);
    { HArgs g = ha(hpo, o1t, px, 4096,1024,1024,1024, 1024,1024,1024);
      g.bias = bo1; g.res = x; g.ldr = 1024; run_h<128,2,64,false,false,false>(g); }

    // ===== cross attention =====
    ln_kernel<<<4096, 128>>>(px, ln2g, ln2b, hh);
    { HArgs g = ha(hh, q2t, hq, 4096,1024,1024,1024, 1024,1024,1024);
      g.qd = dq2; run_h<128,2,64,true,false,false>(g); }
    { HArgs g = ha(chx, kv2t, hk, 154,2048,2048,1024, 1024,1024,1024);
      g.C2 = hv; g.qd = dk2; g.qd2 = dv2; run_h<128,2,64,true,false,true>(g); }
    vtrans<<<dim3(3,2,32), tb>>>(hv, hvt, 77, 96);
    fattn<<<dim3(16,1,32), 256, FSM>>>(hq, hk, hvt, hpo, 2048, 77, 96, dq2, dk2, dw2, dv2);
    { HArgs g = ha(hpo, o2t, px, 4096,1024,1024,1024, 1024,1024,1024);
      g.bias = bo2; g.res = px; g.ldr = 1024; run_h<128,2,64,false,false,false>(g); }

    // ===== GEGLU feed-forward (fused FFN1+GEGLU) =====
    ln_kernel<<<4096, 128>>>(px, ln3g, ln3b, hh);
    { HArgs g = ha(hh, w1t, hgg, 4096,8192,8192,1024, 1024,1024,4096);
      g.bias = b1; run_h<128,2,64,true,true,false>(g); }
    { HArgs g = ha(hgg, w2t, out, 4096,1024,1024,4096, 4096,4096,1024);
      g.bias = b2; g.res = px; g.ldr = 1024; run_h<128,2,64,false,false,false>(g); }
}